// round 3
// baseline (speedup 1.0000x reference)
#include <cuda_runtime.h>

// Problem shape (fixed by the reference setup_inputs)
#define B_  16
#define C_  64
#define H_  64
#define W_  64
#define T_  32
#define HP_ 32
#define WP_ 32
#define NPIX (B_ * C_ * HP_ * WP_)   // 1,048,576 output pixels

// One thread per output pixel (b,c,hp,wp).
// Reads 4 input rows of T_=32 contiguous floats (128B each), averages,
// runs the LIF recurrence over T, writes 32 contiguous floats.
__global__ void __launch_bounds__(256) savgpool_spike_kernel(
    const float* __restrict__ x,
    const float* __restrict__ thresh,
    float* __restrict__ out)
{
    int p = blockIdx.x * blockDim.x + threadIdx.x;
    if (p >= NPIX) return;

    int wp = p & (WP_ - 1);
    int hp = (p >> 5) & (HP_ - 1);
    int bc = p >> 10;                 // b*C + c

    const float th = __ldg(thresh);   // uniform scalar

    // Input row base: (((bc*H + 2*hp)*W + 2*wp) * T)
    size_t base = (((size_t)bc * H_ + 2 * hp) * W_ + 2 * wp) * T_;
    const float4* r0 = (const float4*)(x + base);
    const float4* r1 = (const float4*)(x + base + T_);
    const float4* r2 = (const float4*)(x + base + (size_t)W_ * T_);
    const float4* r3 = (const float4*)(x + base + (size_t)W_ * T_ + T_);

    // Front-batch all 32 LDG.128 for maximum MLP, average into pv[8]
    float4 pv[8];
    #pragma unroll
    for (int i = 0; i < 8; i++) {
        float4 a = r0[i];
        float4 b = r1[i];
        float4 c = r2[i];
        float4 d = r3[i];
        pv[i].x = (a.x + b.x + c.x + d.x) * 0.25f;
        pv[i].y = (a.y + b.y + c.y + d.y) * 0.25f;
        pv[i].z = (a.z + b.z + c.z + d.z) * 0.25f;
        pv[i].w = (a.w + b.w + c.w + d.w) * 0.25f;
    }

    // LIF recurrence: u = u - s*th + p_t ; s = (u > 0)
    // Overwrite pv in place with spikes to save registers.
    float u = 0.0f, s = 0.0f;
    #pragma unroll
    for (int i = 0; i < 8; i++) {
        float* pp = (float*)&pv[i];
        #pragma unroll
        for (int j = 0; j < 4; j++) {
            u = u - s * th + pp[j];
            s = (u > 0.0f) ? 1.0f : 0.0f;
            pp[j] = s;
        }
    }

    // Output: 32 contiguous floats per pixel -> 8 STG.128
    float4* o = (float4*)(out + (size_t)p * T_);
    #pragma unroll
    for (int i = 0; i < 8; i++) o[i] = pv[i];
}

extern "C" void kernel_launch(void* const* d_in, const int* in_sizes, int n_in,
                              void* d_out, int out_size)
{
    const float* x      = (const float*)d_in[0];
    const float* thresh = (const float*)d_in[1];
    float* out          = (float*)d_out;

    const int threads = 256;
    const int blocks  = (NPIX + threads - 1) / threads;
    savgpool_spike_kernel<<<blocks, threads>>>(x, thresh, out);
}

// round 5
// speedup vs baseline: 1.4756x; 1.4756x over previous
#include <cuda_runtime.h>

// Shape fixed by reference setup_inputs
#define B_  16
#define C_  64
#define H_  64
#define W_  64
#define T_  32
#define HP_ 32
#define WP_ 32

// Block: 128 threads; one bc (=b*C+c) and one hp-group g (0..7).
// Output rows hp = 4g..4g+3 (128 pixels), input rows h = 8g..8g+7 (64KB contiguous).
//
// Phase 1: coalesced float4 loads of the full 2x2 quad, pooled value straight
//          to padded smem pooled[pix][tt] (stride 33, conflict-free scatter).
// Phase 2: thread t owns pixel t: batch-LDS its 32 pooled values (conflict-free),
//          LIF recurrence in regs, overwrite row with spikes (in-place, own row).
// Phase 3: coalesced float4 stores of spikes.
__global__ void __launch_bounds__(128) savgpool_spike_kernel(
    const float* __restrict__ x,
    const float* __restrict__ thresh,
    float* __restrict__ out)
{
    __shared__ float sp[128 * 33];      // 16896 B

    const int t   = threadIdx.x;
    const int blk = blockIdx.x;
    const int g   = blk & 7;            // hp group
    const int bc  = blk >> 3;

    const float th = __ldg(thresh);

    // 8 contiguous input rows start here (h = 8g..8g+7); each row = 512 float4
    const float4* __restrict__ x4 =
        (const float4*)(x) + ((size_t)bc * H_ + 8 * g) * (W_ * T_ / 4);

    // ---- Phase 1: full 2x2 pool into padded smem ----
    // 1024 pooled float4 chunks: idx -> hl (0..3), wp (0..31), tt4 (0..7)
    #pragma unroll
    for (int it = 0; it < 8; it++) {
        int idx = it * 128 + t;
        int hl  = idx >> 8;
        int rem = idx & 255;
        int wp  = rem >> 3;
        int tt4 = rem & 7;
        const float4* r0 = x4 + (2 * hl)     * 512 + (2 * wp) * 8 + tt4;
        const float4* r1 = x4 + (2 * hl + 1) * 512 + (2 * wp) * 8 + tt4;
        float4 a = r0[0];
        float4 b = r0[8];               // w-pair partner: +8 float4 = +32 floats
        float4 c = r1[0];
        float4 d = r1[8];
        float* s = &sp[(hl * 32 + wp) * 33 + tt4 * 4];
        s[0] = (a.x + b.x + c.x + d.x) * 0.25f;
        s[1] = (a.y + b.y + c.y + d.y) * 0.25f;
        s[2] = (a.z + b.z + c.z + d.z) * 0.25f;
        s[3] = (a.w + b.w + c.w + d.w) * 0.25f;
    }
    __syncthreads();

    // ---- Phase 2: LIF recurrence, in place on own row ----
    {
        float* row = &sp[t * 33];
        float pbuf[T_];
        #pragma unroll
        for (int tt = 0; tt < T_; tt++) pbuf[tt] = row[tt];

        float u = 0.0f, s = 0.0f;
        #pragma unroll
        for (int tt = 0; tt < T_; tt++) {
            u = u - s * th + pbuf[tt];
            s = (u > 0.0f) ? 1.0f : 0.0f;
            row[tt] = s;
        }
    }
    __syncthreads();

    // ---- Phase 3: coalesced float4 write-out ----
    // Block's output pixels: (bc*32 + 4g + hl, wp), T contiguous floats each
    float4* o4 = (float4*)(out) + (((size_t)bc * HP_ + 4 * g) * WP_) * (T_ / 4);
    #pragma unroll
    for (int it = 0; it < 8; it++) {
        int c   = it * 128 + t;         // 0..1023
        int pix = c >> 3;
        int tt0 = (c & 7) * 4;
        const float* s = &sp[pix * 33 + tt0];
        float4 v;
        v.x = s[0]; v.y = s[1]; v.z = s[2]; v.w = s[3];
        o4[c] = v;
    }
}

extern "C" void kernel_launch(void* const* d_in, const int* in_sizes, int n_in,
                              void* d_out, int out_size)
{
    const float* x      = (const float*)d_in[0];
    const float* thresh = (const float*)d_in[1];
    float* out          = (float*)d_out;

    const int blocks = (B_ * C_) * (HP_ / 4);   // 1024 * 8 = 8192
    savgpool_spike_kernel<<<blocks, 128>>>(x, thresh, out);
}

// round 7
// speedup vs baseline: 1.4810x; 1.0037x over previous
#include <cuda_runtime.h>

// Shape fixed by reference setup_inputs
#define B_  16
#define C_  64
#define H_  64
#define W_  64
#define T_  32
#define HP_ 32
#define WP_ 32

// Block: 128 threads; one bc (=b*C+c) and one hp-group g (0..7).
// WARP-LOCAL pipeline: warp w owns pooled row hl=w end to end:
//   Phase 1: warp w loads input rows 2(4g+w), 2(4g+w)+1 (coalesced float4),
//            computes 2x2 pool, scatters to its own 32 smem rows (stride 33).
//   Phase 2: lane l = pixel (hl=w, wp=l): batch-LDS own row, LIF recurrence
//            in regs, overwrite row with spikes.
//   Phase 3: warp w writes its 32 pixels' spike rows out (coalesced float4).
// No data crosses warps -> only __syncwarp(), no __syncthreads.
__global__ void __launch_bounds__(128) savgpool_spike_kernel(
    const float* __restrict__ x,
    const float* __restrict__ thresh,
    float* __restrict__ out)
{
    __shared__ float sp[128 * 33];      // 16896 B

    const int t    = threadIdx.x;
    const int lane = t & 31;
    const int w    = t >> 5;            // warp id = local hp row hl
    const int blk  = blockIdx.x;
    const int g    = blk & 7;           // hp group
    const int bc   = blk >> 3;

    const float th = __ldg(thresh);

    // Input rows h = 8g..8g+7; each row = 512 float4. Warp w uses rows 2w, 2w+1.
    const float4* __restrict__ x4 =
        (const float4*)(x) + ((size_t)bc * H_ + 8 * g) * (W_ * T_ / 4);
    const float4* __restrict__ r0base = x4 + (2 * w)     * 512;
    const float4* __restrict__ r1base = x4 + (2 * w + 1) * 512;

    // ---- Phase 1: 2x2 pool into this warp's 32 smem rows ----
    // 256 pooled float4 chunks for row hl=w: idx -> wp (0..31), tt4 (0..7)
    #pragma unroll
    for (int it = 0; it < 8; it++) {
        int idx = it * 32 + lane;
        int wp  = idx >> 3;
        int tt4 = idx & 7;
        const float4* p0 = r0base + (2 * wp) * 8 + tt4;
        const float4* p1 = r1base + (2 * wp) * 8 + tt4;
        float4 a = __ldcs(p0);
        float4 b = __ldcs(p0 + 8);      // w-pair partner: +32 floats
        float4 c = __ldcs(p1);
        float4 d = __ldcs(p1 + 8);
        float* s = &sp[(w * 32 + wp) * 33 + tt4 * 4];
        s[0] = (a.x + b.x + c.x + d.x) * 0.25f;
        s[1] = (a.y + b.y + c.y + d.y) * 0.25f;
        s[2] = (a.z + b.z + c.z + d.z) * 0.25f;
        s[3] = (a.w + b.w + c.w + d.w) * 0.25f;
    }
    __syncwarp();

    // ---- Phase 2: LIF recurrence, in place on own row ----
    {
        float* row = &sp[t * 33];       // pixel (hl=w, wp=lane)
        float pbuf[T_];
        #pragma unroll
        for (int tt = 0; tt < T_; tt++) pbuf[tt] = row[tt];

        float u = 0.0f, s = 0.0f;
        #pragma unroll
        for (int tt = 0; tt < T_; tt++) {
            u = u - s * th + pbuf[tt];
            s = (u > 0.0f) ? 1.0f : 0.0f;
            row[tt] = s;
        }
    }
    __syncwarp();

    // ---- Phase 3: coalesced float4 write-out of this warp's 32 pixels ----
    // Block pixels: (bc*32 + 4g + hl, wp); warp w's span = 256 contiguous float4
    float4* o4 = (float4*)(out) + (((size_t)bc * HP_ + 4 * g) * WP_) * (T_ / 4)
               + w * 256;
    #pragma unroll
    for (int it = 0; it < 8; it++) {
        int c   = it * 32 + lane;       // 0..255 within warp's span
        int pix = w * 32 + (c >> 3);
        int tt0 = (c & 7) * 4;
        const float* s = &sp[pix * 33 + tt0];
        float4 v;
        v.x = s[0]; v.y = s[1]; v.z = s[2]; v.w = s[3];
        __stcs(o4 + c, v);
    }
}

extern "C" void kernel_launch(void* const* d_in, const int* in_sizes, int n_in,
                              void* d_out, int out_size)
{
    const float* x      = (const float*)d_in[0];
    const float* thresh = (const float*)d_in[1];
    float* out          = (float*)d_out;

    const int blocks = (B_ * C_) * (HP_ / 4);   // 1024 * 8 = 8192
    savgpool_spike_kernel<<<blocks, 128>>>(x, thresh, out);
}

// round 9
// speedup vs baseline: 1.6713x; 1.1285x over previous
#include <cuda_runtime.h>

// Shape fixed by reference setup_inputs
#define B_  16
#define C_  64
#define H_  64
#define W_  64
#define T_  32
#define HP_ 32
#define WP_ 32

#define NBLK   (B_ * C_ * (HP_ / 4))   // 8192 logical tiles
#define GRIDSZ (148 * 12)              // persistent: ~1 resident wave

// Warp-local pipeline, XOR-swizzled smem, all smem ops 128-bit.
// Logical tile blk -> bc = blk>>3, hp-group g = blk&7.
// Warp w owns pooled row hl=w: input rows 8g+2w, 8g+2w+1.
//
// smem layout (float4 units): row r (0..127) chunk c (0..7) at r*8 + (c ^ (r&7)).
__global__ void __launch_bounds__(128) savgpool_spike_kernel(
    const float* __restrict__ x,
    const float* __restrict__ thresh,
    float* __restrict__ out)
{
    __shared__ float4 sp[128 * 8];      // 16 KB

    const int t    = threadIdx.x;
    const int lane = t & 31;
    const int w    = t >> 5;

    const float th = __ldg(thresh);

    for (int blk = blockIdx.x; blk < NBLK; blk += GRIDSZ) {
        const int g  = blk & 7;
        const int bc = blk >> 3;

        // Input rows h = 8g..8g+7; each row = 512 float4. Warp w: rows 2w, 2w+1.
        const float4* __restrict__ x4 =
            (const float4*)(x) + ((size_t)bc * H_ + 8 * g) * (W_ * T_ / 4);
        const float4* __restrict__ r0base = x4 + (2 * w)     * 512;
        const float4* __restrict__ r1base = x4 + (2 * w + 1) * 512;

        // ---- Phase 1: 2x2 pool -> swizzled smem (STS.128) ----
        #pragma unroll
        for (int it = 0; it < 8; it++) {
            int idx = it * 32 + lane;       // 0..255
            int wp  = idx >> 3;
            int c   = idx & 7;
            const float4* p0 = r0base + (2 * wp) * 8 + c;
            const float4* p1 = p0 + (512 - 0) + 0;  // placeholder (unused)
            (void)p1;
            const float4* q1 = r1base + (2 * wp) * 8 + c;
            float4 a = __ldcs(p0);
            float4 b = __ldcs(p0 + 8);
            float4 cc = __ldcs(q1);
            float4 d = __ldcs(q1 + 8);
            int r = w * 32 + wp;
            float4 v;
            v.x = (a.x + b.x + cc.x + d.x) * 0.25f;
            v.y = (a.y + b.y + cc.y + d.y) * 0.25f;
            v.z = (a.z + b.z + cc.z + d.z) * 0.25f;
            v.w = (a.w + b.w + cc.w + d.w) * 0.25f;
            sp[r * 8 + (c ^ (r & 7))] = v;
        }
        __syncwarp();

        // ---- Phase 2: LIF recurrence in float4 groups (LDS.128/STS.128) ----
        {
            const int r  = t;               // own pixel row
            const int sw = r & 7;
            float4* row = &sp[r * 8];
            float u = 0.0f, s = 0.0f;
            #pragma unroll
            for (int c = 0; c < 8; c++) {
                float4 q = row[c ^ sw];
                float4 v;
                u = u - s * th + q.x;  s = (u > 0.0f) ? 1.0f : 0.0f;  v.x = s;
                u = u - s * th + q.y;  s = (u > 0.0f) ? 1.0f : 0.0f;  v.y = s;
                u = u - s * th + q.z;  s = (u > 0.0f) ? 1.0f : 0.0f;  v.z = s;
                u = u - s * th + q.w;  s = (u > 0.0f) ? 1.0f : 0.0f;  v.w = s;
                row[c ^ sw] = v;
            }
        }
        __syncwarp();

        // ---- Phase 3: coalesced float4 write-out (LDS.128 -> STG.128) ----
        // Warp w's span = 256 contiguous float4 in output.
        float4* o4 = (float4*)(out) + (((size_t)bc * HP_ + 4 * g) * WP_) * (T_ / 4)
                   + w * 256;
        #pragma unroll
        for (int it = 0; it < 8; it++) {
            int cl  = it * 32 + lane;       // 0..255
            int r   = w * 32 + (cl >> 3);
            int c   = cl & 7;
            __stcs(o4 + cl, sp[r * 8 + (c ^ (r & 7))]);
        }
        __syncwarp();                       // protect smem before next tile
    }
}

extern "C" void kernel_launch(void* const* d_in, const int* in_sizes, int n_in,
                              void* d_out, int out_size)
{
    const float* x      = (const float*)d_in[0];
    const float* thresh = (const float*)d_in[1];
    float* out          = (float*)d_out;

    savgpool_spike_kernel<<<GRIDSZ, 128>>>(x, thresh, out);
}